// round 9
// baseline (speedup 1.0000x reference)
#include <cuda_runtime.h>
#include <math.h>

// Problem constants
#define NN   100000
#define EE   1600000
#define CI1  32
#define CO   64
#define KZ   512           // K * C_OUT = 8*64

// ---------------- static device scratch (no allocations allowed) ----------------
// NOTE: these are referenced ONLY from device code (by symbol). Passing them as
// host-side kernel arguments yields the HOST shadow address (ATS-accessible on
// GB300 -> silent wrong-memory traffic). That was the R2/R7 0.1547 bug.
__device__ float  g_z[(size_t)NN * KZ];        // 204.8 MB, fp32 node pre-GEMM
__device__ float  g_agg1[(size_t)NN * CO];
__device__ float  g_agg2[(size_t)NN * CO];
__device__ float  g_t  [(size_t)NN * CO];      // t1 then t2 (pre-BN conv outputs)
__device__ float  g_sp [(size_t)NN * CO];      // skip_pre then skip (in-place)
__device__ float  g_h  [(size_t)NN * CO];      // layer-1 activations
__device__ float  g_deg[NN];
__device__ float  g_stats[6 * 64];             // sum/sumsq for t1, skip, t2
__device__ float  g_coef [6 * 64];             // fused BN scale/shift x3

__device__ __forceinline__ float eluf(float v) {
    return v > 0.f ? v : expm1f(v);
}

// ---------------- zero scratch ----------------
__global__ void zero_kernel() {
    size_t idx = (size_t)blockIdx.x * blockDim.x + threadIdx.x;
    const size_t n1 = (size_t)NN * CO;
    if (idx < n1)                 { g_agg1[idx] = 0.f; return; }
    idx -= n1;
    if (idx < n1)                 { g_agg2[idx] = 0.f; return; }
    idx -= n1;
    if (idx < NN)                 { g_deg[idx] = 0.f; return; }
    idx -= NN;
    if (idx < 6 * 64)             { g_stats[idx] = 0.f; }
}

// ---------------- degree ----------------
__global__ void deg_kernel(const int* __restrict__ ei) {
    int e = blockIdx.x * blockDim.x + threadIdx.x;
    if (e < EE) {
        int dst = __ldg(&ei[EE + e]);
        atomicAdd(&g_deg[dst], 1.0f);
    }
}

// ---------------- node pre-GEMM: g_z[n, k*64+o] = sum_i X[n,i] * W[k,i,o] ----------------
// LAYER 0: X = harness x (param). LAYER 1: X = g_h (device symbol).
template <int CIN, int LAYER>
__global__ __launch_bounds__(512, 1) void zgemm_kernel(const float* __restrict__ Xin,
                                                       const float* __restrict__ Wg) {
    const float* __restrict__ X = (LAYER == 0) ? Xin : (const float*)g_h;
    extern __shared__ float sm[];
    float* Wl = sm;                 // [i][j], j = k*64+o  (CIN*512 floats)
    float* Xs = sm + CIN * KZ;      // [i][m], 32 nodes    (CIN*32 floats)
    const int tid = threadIdx.x;

    // stage W, rearranged from [k][i][o] to [i][k*64+o]
    const float4* Wg4 = (const float4*)Wg;
    const int WN4 = CIN * KZ / 4;
    for (int idx4 = tid; idx4 < WN4; idx4 += 512) {
        float4 v = Wg4[idx4];
        int linear = idx4 * 4;
        int k = linear / (CIN * 64);
        int r = linear - k * CIN * 64;
        int i = r >> 6;
        int o = r & 63;
        *(float4*)&Wl[i * KZ + k * 64 + o] = v;
    }
    // stage X tile transposed: Xs[i*32 + m]
    int n0 = blockIdx.x * 32;
    for (int idx = tid; idx < 32 * CIN; idx += 512) {
        int m = idx / CIN;
        int i = idx - m * CIN;
        Xs[i * 32 + m] = X[(size_t)(n0 + m) * CIN + i];
    }
    __syncthreads();

    const int j = tid;   // output column 0..511
    float acc[32];
#pragma unroll
    for (int m = 0; m < 32; m++) acc[m] = 0.f;

    for (int i = 0; i < CIN; i++) {
        float w = Wl[i * KZ + j];
        const float4* xr = (const float4*)&Xs[i * 32];   // broadcast loads
#pragma unroll
        for (int p = 0; p < 8; p++) {
            float4 xv = xr[p];
            acc[4 * p + 0] = fmaf(w, xv.x, acc[4 * p + 0]);
            acc[4 * p + 1] = fmaf(w, xv.y, acc[4 * p + 1]);
            acc[4 * p + 2] = fmaf(w, xv.z, acc[4 * p + 2]);
            acc[4 * p + 3] = fmaf(w, xv.w, acc[4 * p + 3]);
        }
    }
#pragma unroll
    for (int m = 0; m < 32; m++) {
        g_z[(size_t)(n0 + m) * KZ + j] = acc[m];
    }
}

// ---------------- edge kernel: warp per edge, symbols for z and agg ----------------
template <int LAYER>
__global__ __launch_bounds__(256) void edge_kernel(const int* __restrict__ ei,
                                                   const float* __restrict__ ea) {
    float* __restrict__ agg = (LAYER == 0) ? g_agg1 : g_agg2;
    const float* __restrict__ z = g_z;

    int w = blockIdx.x * 8 + (threadIdx.x >> 5);      // edge id (grid sized exactly)
    int lane = threadIdx.x & 31;
    int src = __ldg(&ei[w]);
    int dst = __ldg(&ei[EE + w]);
    float u0 = __ldg(&ea[3 * w + 0]);
    float u1 = __ldg(&ea[3 * w + 1]);
    float u2 = __ldg(&ea[3 * w + 2]);

    float f0  = (lane & 16) ? u0 : 1.f - u0;          // bit0 of k
    float v1a = 1.f - u1, v2a = 1.f - u2;

    // lanes 0-15: even k, cols o = lane*4..+3 ; lanes 16-31: odd k, same cols
    const float* zp = z + (size_t)src * KZ + lane * 4;
    float4 acc = make_float4(0.f, 0.f, 0.f, 0.f);
#pragma unroll
    for (int t = 0; t < 4; t++) {                     // k = 2t + (lane>=16)
        float bas = f0 * ((t & 1) ? u1 : v1a) * ((t & 2) ? u2 : v2a);
        float4 v = __ldg((const float4*)(zp + t * 128));
        acc.x = fmaf(bas, v.x, acc.x);
        acc.y = fmaf(bas, v.y, acc.y);
        acc.z = fmaf(bas, v.z, acc.z);
        acc.w = fmaf(bas, v.w, acc.w);
    }
    acc.x += __shfl_down_sync(0xffffffffu, acc.x, 16);
    acc.y += __shfl_down_sync(0xffffffffu, acc.y, 16);
    acc.z += __shfl_down_sync(0xffffffffu, acc.z, 16);
    acc.w += __shfl_down_sync(0xffffffffu, acc.w, 16);
    if (lane < 16) {
        float* p = agg + (size_t)dst * CO + lane * 4;
        atomicAdd(p + 0, acc.x);
        atomicAdd(p + 1, acc.y);
        atomicAdd(p + 2, acc.z);
        atomicAdd(p + 3, acc.w);
    }
}

// ---------------- post layer1: t1 = agg1/deg + x@root1 ; sp = x@Wskip ; stats ----------------
__global__ __launch_bounds__(256) void post1_kernel(const float* __restrict__ X,
                                                    const float* __restrict__ root1,
                                                    const float* __restrict__ Wsk) {
    __shared__ float Rl[CI1 * 64];
    __shared__ float Sl[CI1 * 64];
    __shared__ float Xs[128 * CI1];
    int tid = threadIdx.x;
    for (int idx = tid; idx < CI1 * 64; idx += 256) {
        Rl[idx] = root1[idx];
        Sl[idx] = Wsk[idx];
    }
    int n0 = blockIdx.x * 128;
    for (int idx = tid; idx < 128 * CI1; idx += 256) {
        int m = idx >> 5, i = idx & 31;
        int n = n0 + m;
        Xs[idx] = (n < NN) ? X[(size_t)n * CI1 + i] : 0.f;
    }
    __syncthreads();

    int o = tid & 63, g = tid >> 6;
    float s0 = 0.f, s1 = 0.f, s2 = 0.f, s3 = 0.f;
    for (int it = 0; it < 32; it++) {
        int m = g * 32 + it;
        int n = n0 + m;
        if (n >= NN) break;
        float am = 0.f, as = 0.f;
#pragma unroll
        for (int i = 0; i < CI1; i++) {
            float xv = Xs[m * CI1 + i];
            am = fmaf(xv, Rl[i * 64 + o], am);
            as = fmaf(xv, Sl[i * 64 + o], as);
        }
        float inv = 1.f / fmaxf(g_deg[n], 1.f);
        float tm = g_agg1[(size_t)n * CO + o] * inv + am;
        g_t [(size_t)n * CO + o] = tm;
        g_sp[(size_t)n * CO + o] = as;
        s0 += tm; s1 += tm * tm; s2 += as; s3 += as * as;
    }
    atomicAdd(&g_stats[0 * 64 + o], s0);
    atomicAdd(&g_stats[1 * 64 + o], s1);
    atomicAdd(&g_stats[2 * 64 + o], s2);
    atomicAdd(&g_stats[3 * 64 + o], s3);
}

// ---------------- post layer2: t2 = agg2/deg + h@root2 ; stats ----------------
__global__ __launch_bounds__(256) void post2_kernel(const float* __restrict__ root2) {
    __shared__ float Rl[CO * 64];
    __shared__ float Xs[128 * CO];
    int tid = threadIdx.x;
    for (int idx = tid; idx < CO * 64; idx += 256) Rl[idx] = root2[idx];
    int n0 = blockIdx.x * 128;
    for (int idx = tid; idx < 128 * CO; idx += 256) {
        int m = idx >> 6, i = idx & 63;
        int n = n0 + m;
        Xs[idx] = (n < NN) ? g_h[(size_t)n * CO + i] : 0.f;
    }
    __syncthreads();

    int o = tid & 63, g = tid >> 6;
    float s0 = 0.f, s1 = 0.f;
    for (int it = 0; it < 32; it++) {
        int m = g * 32 + it;
        int n = n0 + m;
        if (n >= NN) break;
        float am = 0.f;
#pragma unroll
        for (int i = 0; i < CO; i++) {
            am = fmaf(Xs[m * CO + i], Rl[i * 64 + o], am);
        }
        float inv = 1.f / fmaxf(g_deg[n], 1.f);
        float tm = g_agg2[(size_t)n * CO + o] * inv + am;
        g_t[(size_t)n * CO + o] = tm;
        s0 += tm; s1 += tm * tm;
    }
    atomicAdd(&g_stats[4 * 64 + o], s0);
    atomicAdd(&g_stats[5 * 64 + o], s1);
}

// ---------------- finalize BN coefs ----------------
__global__ void finalize1_kernel(const float* __restrict__ g1, const float* __restrict__ b1,
                                 const float* __restrict__ gs, const float* __restrict__ bs) {
    int o = threadIdx.x;
    const float invN = 1.f / (float)NN;
    float m = g_stats[0 * 64 + o] * invN;
    float v = g_stats[1 * 64 + o] * invN - m * m;
    float a = g1[o] * rsqrtf(v + 1e-5f);
    g_coef[0 * 64 + o] = a;
    g_coef[1 * 64 + o] = b1[o] - m * a;
    m = g_stats[2 * 64 + o] * invN;
    v = g_stats[3 * 64 + o] * invN - m * m;
    a = gs[o] * rsqrtf(v + 1e-5f);
    g_coef[2 * 64 + o] = a;
    g_coef[3 * 64 + o] = bs[o] - m * a;
}

__global__ void finalize2_kernel(const float* __restrict__ g2, const float* __restrict__ b2) {
    int o = threadIdx.x;
    const float invN = 1.f / (float)NN;
    float m = g_stats[4 * 64 + o] * invN;
    float v = g_stats[5 * 64 + o] * invN - m * m;
    float a = g2[o] * rsqrtf(v + 1e-5f);
    g_coef[4 * 64 + o] = a;
    g_coef[5 * 64 + o] = b2[o] - m * a;
}

// ---------------- elementwise applies ----------------
__global__ __launch_bounds__(256) void apply1_kernel() {
    size_t idx = (size_t)blockIdx.x * 256 + threadIdx.x;   // < NN*64
    int o = (int)(idx & 63);
    float hv = g_t[idx] * g_coef[o] + g_coef[64 + o];
    g_h[idx] = eluf(hv);
    float sv = g_sp[idx] * g_coef[128 + o] + g_coef[192 + o];
    g_sp[idx] = sv;                                        // skip (in-place)
}

__global__ __launch_bounds__(256) void apply2_kernel(float* __restrict__ out) {
    size_t idx = (size_t)blockIdx.x * 256 + threadIdx.x;
    int o = (int)(idx & 63);
    float v = g_t[idx] * g_coef[256 + o] + g_coef[320 + o] + g_sp[idx];
    out[idx] = eluf(v);
}

// ---------------- launch ----------------
extern "C" void kernel_launch(void* const* d_in, const int* in_sizes, int n_in,
                              void* d_out, int out_size) {
    const float* x     = (const float*)d_in[0];
    const int*   ei    = (const int*)  d_in[1];
    const float* ea    = (const float*)d_in[2];
    const float* W1    = (const float*)d_in[3];
    const float* root1 = (const float*)d_in[4];
    const float* g1    = (const float*)d_in[5];
    const float* b1    = (const float*)d_in[6];
    const float* W2    = (const float*)d_in[7];
    const float* root2 = (const float*)d_in[8];
    const float* g2    = (const float*)d_in[9];
    const float* b2    = (const float*)d_in[10];
    const float* Wsk   = (const float*)d_in[11];
    const float* gsk   = (const float*)d_in[12];
    const float* bsk   = (const float*)d_in[13];
    float* out = (float*)d_out;

    // opt in to large dynamic smem (idempotent, capture-safe: not a stream op)
    cudaFuncSetAttribute(zgemm_kernel<CI1, 0>, cudaFuncAttributeMaxDynamicSharedMemorySize, 160 * 1024);
    cudaFuncSetAttribute(zgemm_kernel<CO, 1>,  cudaFuncAttributeMaxDynamicSharedMemorySize, 160 * 1024);

    const size_t zero_total = (size_t)NN * CO * 2 + NN + 6 * 64;
    zero_kernel<<<(int)((zero_total + 255) / 256), 256>>>();
    deg_kernel<<<EE / 256, 256>>>(ei);

    // ---- layer 1 ----
    zgemm_kernel<CI1, 0><<<NN / 32, 512, CI1 * (KZ + 32) * sizeof(float)>>>(x, W1);
    edge_kernel<0><<<EE / 8, 256>>>(ei, ea);
    post1_kernel<<<(NN + 127) / 128, 256>>>(x, root1, Wsk);
    finalize1_kernel<<<1, 64>>>(g1, b1, gsk, bsk);
    apply1_kernel<<<NN * CO / 256, 256>>>();

    // ---- layer 2 ----
    zgemm_kernel<CO, 1><<<NN / 32, 512, CO * (KZ + 32) * sizeof(float)>>>(nullptr, W2);
    edge_kernel<1><<<EE / 8, 256>>>(ei, ea);
    post2_kernel<<<(NN + 127) / 128, 256>>>(root2);
    finalize2_kernel<<<1, 64>>>(g2, b2);
    apply2_kernel<<<NN * CO / 256, 256>>>(out);
}

// round 14
// speedup vs baseline: 1.3527x; 1.3527x over previous
#include <cuda_runtime.h>
#include <cuda_fp16.h>
#include <math.h>

// Problem constants
#define NN   100000
#define EE   1600000
#define CI1  32
#define CO   64
#define KZ   512           // K * C_OUT = 8*64

// ---------------- static device scratch (no allocations allowed) ----------------
// Referenced ONLY by symbol inside device code (host-passing a __device__ symbol
// yields the HOST shadow on GB300/ATS -> the R2/R7 0.1547 bug).
__device__ __half g_z[(size_t)NN * KZ];        // 102.4 MB, fp16 node pre-GEMM
__device__ float  g_agg1[(size_t)NN * CO];
__device__ float  g_agg2[(size_t)NN * CO];
__device__ float  g_t  [(size_t)NN * CO];      // t1 then t2 (pre-BN conv outputs)
__device__ float  g_sp [(size_t)NN * CO];      // skip_pre then skip (in-place)
__device__ float  g_h  [(size_t)NN * CO];      // layer-1 activations
__device__ float  g_deg[NN];
__device__ float  g_stats[6 * 64];             // sum/sumsq for t1, skip, t2
__device__ float  g_coef [6 * 64];             // fused BN scale/shift x3

__device__ __forceinline__ float eluf(float v) {
    return v > 0.f ? v : expm1f(v);
}

__device__ __forceinline__ unsigned long long ffma2(unsigned long long a,
                                                    unsigned long long b,
                                                    unsigned long long c) {
    unsigned long long d;
    asm("fma.rn.f32x2 %0, %1, %2, %3;" : "=l"(d) : "l"(a), "l"(b), "l"(c));
    return d;
}

// ---------------- zero scratch ----------------
__global__ void zero_kernel() {
    size_t idx = (size_t)blockIdx.x * blockDim.x + threadIdx.x;
    const size_t n1 = (size_t)NN * CO;
    if (idx < n1)                 { g_agg1[idx] = 0.f; return; }
    idx -= n1;
    if (idx < n1)                 { g_agg2[idx] = 0.f; return; }
    idx -= n1;
    if (idx < NN)                 { g_deg[idx] = 0.f; return; }
    idx -= NN;
    if (idx < 6 * 64)             { g_stats[idx] = 0.f; }
}

// ---------------- degree ----------------
__global__ void deg_kernel(const int* __restrict__ ei) {
    int e = blockIdx.x * blockDim.x + threadIdx.x;
    if (e < EE) {
        int dst = __ldg(&ei[EE + e]);
        atomicAdd(&g_deg[dst], 1.0f);
    }
}

// ---------------- node pre-GEMM: g_z[n, k*64+o] = sum_i X[n,i] * W[k,i,o] (fp16 out) ----
// LAYER 0: X = harness x (param). LAYER 1: X = g_h (device symbol).
template <int CIN, int LAYER>
__global__ __launch_bounds__(512, 1) void zgemm_kernel(const float* __restrict__ Xin,
                                                       const float* __restrict__ Wg) {
    const float* __restrict__ X = (LAYER == 0) ? Xin : (const float*)g_h;
    extern __shared__ float sm[];
    float* Wl = sm;                 // [i][j], j = k*64+o  (CIN*512 floats)
    float* Xs = sm + CIN * KZ;      // [i][m], 32 nodes    (CIN*32 floats)
    const int tid = threadIdx.x;

    // stage W, rearranged from [k][i][o] to [i][k*64+o]
    const float4* Wg4 = (const float4*)Wg;
    const int WN4 = CIN * KZ / 4;
    for (int idx4 = tid; idx4 < WN4; idx4 += 512) {
        float4 v = Wg4[idx4];
        int linear = idx4 * 4;
        int k = linear / (CIN * 64);
        int r = linear - k * CIN * 64;
        int i = r >> 6;
        int o = r & 63;
        *(float4*)&Wl[i * KZ + k * 64 + o] = v;
    }
    // stage X tile transposed: Xs[i*32 + m]
    int n0 = blockIdx.x * 32;
    for (int idx = tid; idx < 32 * CIN; idx += 512) {
        int m = idx / CIN;
        int i = idx - m * CIN;
        Xs[i * 32 + m] = X[(size_t)(n0 + m) * CIN + i];
    }
    __syncthreads();

    const int j = tid;   // output column 0..511
    unsigned long long acc[16];   // 16 x f32x2 = 32 nodes
#pragma unroll
    for (int p = 0; p < 16; p++) acc[p] = 0ull;

#pragma unroll 4
    for (int i = 0; i < CIN; i++) {
        float w = Wl[i * KZ + j];
        unsigned long long wp;
        asm("mov.b64 %0, {%1, %1};" : "=l"(wp) : "f"(w));
        const unsigned long long* xr = (const unsigned long long*)&Xs[i * 32];
#pragma unroll
        for (int p = 0; p < 16; p++) {
            acc[p] = ffma2(wp, xr[p], acc[p]);   // 2 nodes per packed FMA
        }
    }
#pragma unroll
    for (int p = 0; p < 16; p++) {
        float lo, hi;
        asm("mov.b64 {%0, %1}, %2;" : "=f"(lo), "=f"(hi) : "l"(acc[p]));
        g_z[(size_t)(n0 + 2 * p)     * KZ + j] = __float2half_rn(lo);
        g_z[(size_t)(n0 + 2 * p + 1) * KZ + j] = __float2half_rn(hi);
    }
}

// ---------------- edge kernel: warp per edge (fp16 gather, red.v4 scatter) ----------------
template <int LAYER>
__global__ __launch_bounds__(256) void edge_kernel(const int* __restrict__ ei,
                                                   const float* __restrict__ ea) {
    float* __restrict__ agg = (LAYER == 0) ? g_agg1 : g_agg2;

    int w = blockIdx.x * 8 + (threadIdx.x >> 5);      // edge id (grid sized exactly)
    int lane = threadIdx.x & 31;
    int src = __ldg(&ei[w]);
    int dst = __ldg(&ei[EE + w]);
    float u0 = __ldg(&ea[3 * w + 0]);
    float u1 = __ldg(&ea[3 * w + 1]);
    float u2 = __ldg(&ea[3 * w + 2]);

    float f0  = (lane & 16) ? u0 : 1.f - u0;          // bit0 of k
    float v1a = 1.f - u1, v2a = 1.f - u2;

    // lanes 0-15: even k, cols o = lane*4..+3 ; lanes 16-31: odd k (+64 halfs), same cols
    const __half* zp = g_z + (size_t)src * KZ + lane * 4;
    float4 acc = make_float4(0.f, 0.f, 0.f, 0.f);
#pragma unroll
    for (int t = 0; t < 4; t++) {                     // k = 2t + (lane>=16)
        float bas = f0 * ((t & 1) ? u1 : v1a) * ((t & 2) ? u2 : v2a);
        uint2 raw = __ldg((const uint2*)(zp + t * 128));   // 4 halfs
        float2 a = __half22float2(*reinterpret_cast<__half2*>(&raw.x));
        float2 b = __half22float2(*reinterpret_cast<__half2*>(&raw.y));
        acc.x = fmaf(bas, a.x, acc.x);
        acc.y = fmaf(bas, a.y, acc.y);
        acc.z = fmaf(bas, b.x, acc.z);
        acc.w = fmaf(bas, b.y, acc.w);
    }
    acc.x += __shfl_down_sync(0xffffffffu, acc.x, 16);
    acc.y += __shfl_down_sync(0xffffffffu, acc.y, 16);
    acc.z += __shfl_down_sync(0xffffffffu, acc.z, 16);
    acc.w += __shfl_down_sync(0xffffffffu, acc.w, 16);
    if (lane < 16) {
        float* p = agg + (size_t)dst * CO + lane * 4;     // 16B aligned
        asm volatile("red.global.add.v4.f32 [%0], {%1, %2, %3, %4};"
                     :: "l"(p), "f"(acc.x), "f"(acc.y), "f"(acc.z), "f"(acc.w)
                     : "memory");
    }
}

// ---------------- post layer1: t1 = agg1/deg + x@root1 ; sp = x@Wskip ; stats ----------------
__global__ __launch_bounds__(256) void post1_kernel(const float* __restrict__ X,
                                                    const float* __restrict__ root1,
                                                    const float* __restrict__ Wsk) {
    __shared__ float Rl[CI1 * 64];
    __shared__ float Sl[CI1 * 64];
    __shared__ float Xs[128 * CI1];
    int tid = threadIdx.x;
    for (int idx = tid; idx < CI1 * 64; idx += 256) {
        Rl[idx] = root1[idx];
        Sl[idx] = Wsk[idx];
    }
    int n0 = blockIdx.x * 128;
    for (int idx = tid; idx < 128 * CI1; idx += 256) {
        int m = idx >> 5, i = idx & 31;
        int n = n0 + m;
        Xs[idx] = (n < NN) ? X[(size_t)n * CI1 + i] : 0.f;
    }
    __syncthreads();

    int o = tid & 63, g = tid >> 6;
    float s0 = 0.f, s1 = 0.f, s2 = 0.f, s3 = 0.f;
    for (int it = 0; it < 32; it++) {
        int m = g * 32 + it;
        int n = n0 + m;
        if (n >= NN) break;
        float am = 0.f, as = 0.f;
#pragma unroll
        for (int i = 0; i < CI1; i++) {
            float xv = Xs[m * CI1 + i];
            am = fmaf(xv, Rl[i * 64 + o], am);
            as = fmaf(xv, Sl[i * 64 + o], as);
        }
        float inv = 1.f / fmaxf(g_deg[n], 1.f);
        float tm = g_agg1[(size_t)n * CO + o] * inv + am;
        g_t [(size_t)n * CO + o] = tm;
        g_sp[(size_t)n * CO + o] = as;
        s0 += tm; s1 += tm * tm; s2 += as; s3 += as * as;
    }
    atomicAdd(&g_stats[0 * 64 + o], s0);
    atomicAdd(&g_stats[1 * 64 + o], s1);
    atomicAdd(&g_stats[2 * 64 + o], s2);
    atomicAdd(&g_stats[3 * 64 + o], s3);
}

// ---------------- post layer2: t2 = agg2/deg + h@root2 ; stats ----------------
__global__ __launch_bounds__(256) void post2_kernel(const float* __restrict__ root2) {
    __shared__ float Rl[CO * 64];
    __shared__ float Xs[128 * CO];
    int tid = threadIdx.x;
    for (int idx = tid; idx < CO * 64; idx += 256) Rl[idx] = root2[idx];
    int n0 = blockIdx.x * 128;
    for (int idx = tid; idx < 128 * CO; idx += 256) {
        int m = idx >> 6, i = idx & 63;
        int n = n0 + m;
        Xs[idx] = (n < NN) ? g_h[(size_t)n * CO + i] : 0.f;
    }
    __syncthreads();

    int o = tid & 63, g = tid >> 6;
    float s0 = 0.f, s1 = 0.f;
    for (int it = 0; it < 32; it++) {
        int m = g * 32 + it;
        int n = n0 + m;
        if (n >= NN) break;
        float am = 0.f;
#pragma unroll
        for (int i = 0; i < CO; i++) {
            am = fmaf(Xs[m * CO + i], Rl[i * 64 + o], am);
        }
        float inv = 1.f / fmaxf(g_deg[n], 1.f);
        float tm = g_agg2[(size_t)n * CO + o] * inv + am;
        g_t[(size_t)n * CO + o] = tm;
        s0 += tm; s1 += tm * tm;
    }
    atomicAdd(&g_stats[4 * 64 + o], s0);
    atomicAdd(&g_stats[5 * 64 + o], s1);
}

// ---------------- finalize BN coefs ----------------
__global__ void finalize1_kernel(const float* __restrict__ g1, const float* __restrict__ b1,
                                 const float* __restrict__ gs, const float* __restrict__ bs) {
    int o = threadIdx.x;
    const float invN = 1.f / (float)NN;
    float m = g_stats[0 * 64 + o] * invN;
    float v = g_stats[1 * 64 + o] * invN - m * m;
    float a = g1[o] * rsqrtf(v + 1e-5f);
    g_coef[0 * 64 + o] = a;
    g_coef[1 * 64 + o] = b1[o] - m * a;
    m = g_stats[2 * 64 + o] * invN;
    v = g_stats[3 * 64 + o] * invN - m * m;
    a = gs[o] * rsqrtf(v + 1e-5f);
    g_coef[2 * 64 + o] = a;
    g_coef[3 * 64 + o] = bs[o] - m * a;
}

__global__ void finalize2_kernel(const float* __restrict__ g2, const float* __restrict__ b2) {
    int o = threadIdx.x;
    const float invN = 1.f / (float)NN;
    float m = g_stats[4 * 64 + o] * invN;
    float v = g_stats[5 * 64 + o] * invN - m * m;
    float a = g2[o] * rsqrtf(v + 1e-5f);
    g_coef[4 * 64 + o] = a;
    g_coef[5 * 64 + o] = b2[o] - m * a;
}

// ---------------- elementwise applies ----------------
__global__ __launch_bounds__(256) void apply1_kernel() {
    size_t idx = (size_t)blockIdx.x * 256 + threadIdx.x;   // < NN*64
    int o = (int)(idx & 63);
    float hv = g_t[idx] * g_coef[o] + g_coef[64 + o];
    g_h[idx] = eluf(hv);
    float sv = g_sp[idx] * g_coef[128 + o] + g_coef[192 + o];
    g_sp[idx] = sv;                                        // skip (in-place)
}

__global__ __launch_bounds__(256) void apply2_kernel(float* __restrict__ out) {
    size_t idx = (size_t)blockIdx.x * 256 + threadIdx.x;
    int o = (int)(idx & 63);
    float v = g_t[idx] * g_coef[256 + o] + g_coef[320 + o] + g_sp[idx];
    out[idx] = eluf(v);
}

// ---------------- launch ----------------
extern "C" void kernel_launch(void* const* d_in, const int* in_sizes, int n_in,
                              void* d_out, int out_size) {
    const float* x     = (const float*)d_in[0];
    const int*   ei    = (const int*)  d_in[1];
    const float* ea    = (const float*)d_in[2];
    const float* W1    = (const float*)d_in[3];
    const float* root1 = (const float*)d_in[4];
    const float* g1    = (const float*)d_in[5];
    const float* b1    = (const float*)d_in[6];
    const float* W2    = (const float*)d_in[7];
    const float* root2 = (const float*)d_in[8];
    const float* g2    = (const float*)d_in[9];
    const float* b2    = (const float*)d_in[10];
    const float* Wsk   = (const float*)d_in[11];
    const float* gsk   = (const float*)d_in[12];
    const float* bsk   = (const float*)d_in[13];
    float* out = (float*)d_out;

    // opt in to large dynamic smem (idempotent, capture-safe: not a stream op)
    cudaFuncSetAttribute(zgemm_kernel<CI1, 0>, cudaFuncAttributeMaxDynamicSharedMemorySize, 160 * 1024);
    cudaFuncSetAttribute(zgemm_kernel<CO, 1>,  cudaFuncAttributeMaxDynamicSharedMemorySize, 160 * 1024);

    const size_t zero_total = (size_t)NN * CO * 2 + NN + 6 * 64;
    zero_kernel<<<(int)((zero_total + 255) / 256), 256>>>();
    deg_kernel<<<EE / 256, 256>>>(ei);

    // ---- layer 1 ----
    zgemm_kernel<CI1, 0><<<NN / 32, 512, CI1 * (KZ + 32) * sizeof(float)>>>(x, W1);
    edge_kernel<0><<<EE / 8, 256>>>(ei, ea);
    post1_kernel<<<(NN + 127) / 128, 256>>>(x, root1, Wsk);
    finalize1_kernel<<<1, 64>>>(g1, b1, gsk, bsk);
    apply1_kernel<<<NN * CO / 256, 256>>>();

    // ---- layer 2 ----
    zgemm_kernel<CO, 1><<<NN / 32, 512, CO * (KZ + 32) * sizeof(float)>>>(nullptr, W2);
    edge_kernel<1><<<EE / 8, 256>>>(ei, ea);
    post2_kernel<<<(NN + 127) / 128, 256>>>(root2);
    finalize2_kernel<<<1, 64>>>(g2, b2);
    apply2_kernel<<<NN * CO / 256, 256>>>(out);
}